// round 17
// baseline (speedup 1.0000x reference)
#include <cuda_runtime.h>
#include <cuda_fp16.h>
#include <math.h>
#include <stdint.h>

#define NBR 4
#define Dd 256
#define SDIM 64
#define MEAS 320
#define MH 128
#define RH 64
#define UD 16
#define NOBS 25
#define BSZ 32768
#define HALL 512
#define K3P 288
#define N2 288
#define TM 64

__device__ __half  g_W1h[HALL * MEAS];
__device__ uint8_t g_W1l8[HALL * MEAS];
__device__ uint8_t g_W1h8[HALL * MEAS];
__device__ __half  g_W2h[Dd * MH];
__device__ uint8_t g_W2l8[Dd * MH];
__device__ uint8_t g_W2h8[Dd * MH];
__device__ __half  g_B3h[N2 * K3P];
__device__ uint8_t g_B3l8[N2 * K3P];
__device__ uint8_t g_B3h8[N2 * K3P];

#define HSTR 1072
#define OFF_H8L 68608
#define OFF_H8H 106496
#define H8STR 592
#define OFF_BB 144384
#define BBUF 13824
#define OFF_B8L 172032
#define OFF_B8H 185856
#define OFF_AB 199680
#define ABUF 3072
#define OFF_A8L 205824
#define OFF_A8H 208384
#define OFF_SU 210944
#define OFF_LN 215040
#define SMEM_TOTAL 217088
#define INV2048 4.8828125e-4f

#define CPA(dst, src) asm volatile("cp.async.cg.shared.global [%0], [%1], 16;" :: "r"(dst), "l"(src))
#define CPC()  asm volatile("cp.async.commit_group;")
#define CPW1() asm volatile("cp.async.wait_group 1;")
#define CPW0() asm volatile("cp.async.wait_group 0;")
#define LDSM4(r, a) \
    asm volatile("ldmatrix.sync.aligned.m8n8.x4.shared.b16 {%0,%1,%2,%3}, [%4];" \
        : "=r"((r)[0]), "=r"((r)[1]), "=r"((r)[2]), "=r"((r)[3]) : "r"(a))
#define LDSM2(r, a) \
    asm volatile("ldmatrix.sync.aligned.m8n8.x2.shared.b16 {%0,%1}, [%2];" \
        : "=r"((r)[0]), "=r"((r)[1]) : "r"(a))

__device__ __forceinline__ void mma_f32(float* d, const uint32_t* a, const uint32_t* b) {
    asm volatile("mma.sync.aligned.m16n8k16.row.col.f32.f16.f16.f32 "
        "{%0,%1,%2,%3},{%4,%5,%6,%7},{%8,%9},{%0,%1,%2,%3};\n"
        : "+f"(d[0]), "+f"(d[1]), "+f"(d[2]), "+f"(d[3])
        : "r"(a[0]), "r"(a[1]), "r"(a[2]), "r"(a[3]), "r"(b[0]), "r"(b[1]));
}
__device__ __forceinline__ void mma_e4(float* d, const uint32_t* a, const uint32_t* b) {
    asm volatile("mma.sync.aligned.m16n8k32.row.col.f32.e4m3.e4m3.f32 "
        "{%0,%1,%2,%3},{%4,%5,%6,%7},{%8,%9},{%0,%1,%2,%3};\n"
        : "+f"(d[0]), "+f"(d[1]), "+f"(d[2]), "+f"(d[3])
        : "r"(a[0]), "r"(a[1]), "r"(a[2]), "r"(a[3]), "r"(b[0]), "r"(b[1]));
}
__device__ __forceinline__ uint32_t lds32(uint32_t a) {
    uint32_t v; asm volatile("ld.shared.b32 %0, [%1];" : "=r"(v) : "r"(a)); return v;
}
__device__ __forceinline__ uint16_t pack8(float b0, float b1) {   // low byte = b0
    uint16_t r; asm("cvt.rn.satfinite.e4m3x2.f32 %0, %1, %2;" : "=h"(r) : "f"(b1), "f"(b0)); return r;
}
__device__ __forceinline__ uint32_t pack8x4(float b0, float b1, float b2, float b3) {
    return (uint32_t)pack8(b0, b1) | ((uint32_t)pack8(b2, b3) << 16);
}
__device__ __forceinline__ uint32_t packh(__half a, __half b) {
    return (uint32_t)__half_as_ushort(a) | ((uint32_t)__half_as_ushort(b) << 16);
}
__device__ __forceinline__ uint32_t smem_u32(const void* p) {
    uint32_t a;
    asm("{ .reg .u64 t; cvta.to.shared.u64 t, %1; cvt.u32.u64 %0, t; }" : "=r"(a) : "l"(p));
    return a;
}
__device__ __forceinline__ void store3(float v, __half* h16, uint8_t* l8, uint8_t* h8) {
    __half h = __float2half_rn(v);
    *h16 = h;
    *l8 = (uint8_t)pack8((v - __half2float(h)) * 2048.f, 0.f);
    *h8 = (uint8_t)pack8(v, 0.f);
}

// ======================= precompute =======================
__global__ void preK(const float* __restrict__ W1, const float* __restrict__ gates,
                     const float* __restrict__ W2, const float* __restrict__ Wout,
                     const float* __restrict__ Bmat, const float* __restrict__ C,
                     const float* __restrict__ Dm) {
    int bid = blockIdx.x, tid = threadIdx.x;
    if (bid < 640) {
        int e = bid * 256 + tid;
        int row = e / MEAS, k = e % MEAS, n = row >> 7;
        float sc = 1.f;
        if (k < Dd) sc = 1.f / (1.f + expf(-gates[n * Dd + k]));
        store3(W1[e] * sc, &g_W1h[e], &g_W1l8[e], &g_W1h8[e]);
    } else if (bid < 768) {
        int e = (bid - 640) * 256 + tid;
        store3(W2[e], &g_W2h[e], &g_W2l8[e], &g_W2h8[e]);
    } else if (bid < 1056) {                       // B3 z rows (d<256), 288 cols
        int e = (bid - 768) * 256 + tid;
        int d = e / K3P, c = e % K3P;
        float s = 0.f;
        if (c < 256) {
            int n = c >> 6, j = c & 63;
            const float* wr = Wout + (n * Dd + d) * RH;
            const float* br = Bmat + n * RH * (RH + UD) + j;
            #pragma unroll 8
            for (int r = 0; r < RH; r++) s += wr[r] * br[r * (RH + UD)];
        } else if (c < 272) {
            int u = c - 256;
            for (int n = 0; n < NBR; n++) {
                const float* wr = Wout + (n * Dd + d) * RH;
                const float* br = Bmat + n * RH * (RH + UD) + RH + u;
                #pragma unroll 8
                for (int r = 0; r < RH; r++) s += wr[r] * br[r * (RH + UD)];
            }
        }
        store3(s, &g_B3h[e], &g_B3l8[e], &g_B3h8[e]);
    } else if (bid < 1056 + NOBS) {                // yt rows via CW = C @ Wout
        int o = bid - 1056;
        __shared__ float sCW[256];
        {
            int n = tid >> 6, r = tid & 63;
            const float* cr = C + o * Dd;
            const float* wp = Wout + n * Dd * RH + r;
            float s = 0.f;
            #pragma unroll 8
            for (int d = 0; d < Dd; d++) s += cr[d] * wp[d * RH];
            sCW[tid] = s;
        }
        __syncthreads();
        for (int c = tid; c < K3P; c += 256) {
            float v = 0.f;
            if (c < 256) {
                int n = c >> 6, j = c & 63;
                const float* br = Bmat + n * RH * (RH + UD) + j;
                #pragma unroll 8
                for (int r = 0; r < RH; r++) v += sCW[n * 64 + r] * br[r * (RH + UD)];
            } else if (c < 272) {
                int u = c - 256;
                v = Dm[o * UD + u];
                for (int n = 0; n < NBR; n++) {
                    const float* br = Bmat + n * RH * (RH + UD) + RH + u;
                    #pragma unroll 8
                    for (int r = 0; r < RH; r++) v += sCW[n * 64 + r] * br[r * (RH + UD)];
                }
            }
            int e = (256 + o) * K3P + c;
            store3(v, &g_B3h[e], &g_B3l8[e], &g_B3h8[e]);
        }
    } else {                                       // pad rows 281..287
        int e = (bid - 1056 - NOBS) * 256 + tid;
        if (e < 7 * K3P) {
            int idx2 = (281 + e / K3P) * K3P + (e % K3P);
            g_B3h[idx2] = __float2half(0.f);
            g_B3l8[idx2] = 0; g_B3h8[idx2] = 0;
        }
    }
}

// ======================= main kernel: 512 threads =======================
__global__ __launch_bounds__(512, 1) void skolr8(
    const float* __restrict__ z_dyn, const float* __restrict__ z_static,
    const float* __restrict__ dtp,   const float* __restrict__ ut,
    const float* __restrict__ b1g,   const float* __restrict__ gammag,
    const float* __restrict__ betag, const float* __restrict__ b2g,
    float* __restrict__ out)
{
    extern __shared__ char sm[];
    const uint32_t smb = smem_u32(sm);
    const int tid = threadIdx.x, w = tid >> 5, lane = tid & 31;
    const int wm = w >> 2, wn = w & 3;
    const int g = lane >> 2, t4 = lane & 3;
    const int row0 = blockIdx.x * TM;
    const float dt = dtp[0];

    const int sub = lane >> 3;
    const uint32_t aRow = ((uint32_t)(sub & 1)) * 8 + (lane & 7);
    const uint32_t aCh  = ((uint32_t)(sub >> 1)) * 16;
    const uint32_t bRow = ((uint32_t)(sub >> 1)) * 8 + (lane & 7);
    const uint32_t bCh  = ((uint32_t)(sub & 1)) * 16;

    float* su  = (float*)(sm + OFF_SU);
    float* lns = (float*)(sm + OFF_LN);
    float* lnq = lns + 256;

    if (tid < 256) {
        int m = tid >> 2, q = tid & 3;
        float4 f = *(const float4*)&ut[(size_t)(row0 + m) * UD + q * 4];
        f.x *= dt; f.y *= dt; f.z *= dt; f.w *= dt;
        *(float4*)&su[m * UD + q * 4] = f;
    }

    // ================= GEMM1 (2 halves) + fused LN/GELU =================
    for (int p = 0; p < 2; p++) {
        float acc[8][4], cf[8][4];
        #pragma unroll
        for (int i = 0; i < 8; i++)
            #pragma unroll
            for (int j = 0; j < 4; j++) { acc[i][j] = 0.f; cf[i][j] = 0.f; }

        #define STAGE1(kc_, buf_) do { \
            int _kc = (kc_), _bf = (buf_); \
            if (tid < 256) { int m = tid >> 2, q = tid & 3; \
              float4 f = (_kc < 16) \
                ? *(const float4*)&z_dyn[(size_t)(row0 + m) * Dd + _kc * 16 + q * 4] \
                : *(const float4*)&z_static[(size_t)(row0 + m) * SDIM + (_kc - 16) * 16 + q * 4]; \
              __half h0 = __float2half_rn(f.x), h1 = __float2half_rn(f.y); \
              __half h2 = __float2half_rn(f.z), h3 = __float2half_rn(f.w); \
              uint2 hp; hp.x = packh(h0, h1); hp.y = packh(h2, h3); \
              *(uint2*)(sm + OFF_AB + _bf * ABUF + m * 48 + q * 8) = hp; \
              if (_kc & 1) { \
                float l0 = (f.x - __half2float(h0)) * 2048.f, l1 = (f.y - __half2float(h1)) * 2048.f; \
                float l2 = (f.z - __half2float(h2)) * 2048.f, l3 = (f.w - __half2float(h3)) * 2048.f; \
                *(uint32_t*)(sm + OFF_A8L + m * 40 + 16 + q * 4) = pack8x4(l0, l1, l2, l3); \
                *(uint32_t*)(sm + OFF_A8H + m * 40 + 16 + q * 4) = pack8x4(f.x, f.y, f.z, f.w); \
                int pk = _kc - 1; \
                float4 f2 = (pk < 16) \
                  ? *(const float4*)&z_dyn[(size_t)(row0 + m) * Dd + pk * 16 + q * 4] \
                  : *(const float4*)&z_static[(size_t)(row0 + m) * SDIM + (pk - 16) * 16 + q * 4]; \
                __half e0 = __float2half_rn(f2.x), e1 = __float2half_rn(f2.y); \
                __half e2 = __float2half_rn(f2.z), e3 = __float2half_rn(f2.w); \
                float m0 = (f2.x - __half2float(e0)) * 2048.f, m1 = (f2.y - __half2float(e1)) * 2048.f; \
                float m2 = (f2.z - __half2float(e2)) * 2048.f, m3 = (f2.w - __half2float(e3)) * 2048.f; \
                *(uint32_t*)(sm + OFF_A8L + m * 40 + q * 4) = pack8x4(m0, m1, m2, m3); \
                *(uint32_t*)(sm + OFF_A8H + m * 40 + q * 4) = pack8x4(f2.x, f2.y, f2.z, f2.w); \
              } } \
            { int n = tid & 255, h16 = tid >> 8; \
              const __half* src = g_W1h + (size_t)(p * 256 + n) * MEAS + _kc * 16 + h16 * 8; \
              CPA(smb + OFF_BB + _bf * BBUF + n * 48 + h16 * 16, src); } \
            if (_kc & 1) { \
              _Pragma("unroll") \
              for (int t = 0; t < 2; t++) { \
                int comp = tid + t * 512; \
                int n = comp & 255, h16 = (comp >> 8) & 1, pl = comp >> 9; \
                const uint8_t* src = (pl ? g_W1h8 : g_W1l8) + (size_t)(p * 256 + n) * MEAS + (_kc >> 1) * 32 + h16 * 16; \
                CPA(smb + (pl ? OFF_B8H : OFF_B8L) + n * 48 + h16 * 16, src); \
              } } \
        } while (0)

        STAGE1(0, 0); CPC();
        for (int kc = 0; kc < 20; kc++) {
            if (kc < 19) { STAGE1(kc + 1, (kc + 1) & 1); CPC(); CPW1(); } else { CPW0(); }
            __syncthreads();
            const int buf = kc & 1;
            uint32_t ah[4], a8l[4], a8h[4];
            LDSM4(ah, smb + OFF_AB + buf * ABUF + (wm * 16 + aRow) * 48 + aCh);
            if (kc & 1) {
                uint32_t r0 = smb + OFF_A8L + (wm * 16 + g) * 40 + t4 * 4;
                a8l[0] = lds32(r0); a8l[1] = lds32(r0 + 320); a8l[2] = lds32(r0 + 16); a8l[3] = lds32(r0 + 336);
                r0 += OFF_A8H - OFF_A8L;
                a8h[0] = lds32(r0); a8h[1] = lds32(r0 + 320); a8h[2] = lds32(r0 + 16); a8h[3] = lds32(r0 + 336);
            }
            uint32_t bbase = smb + OFF_BB + buf * BBUF + (wn * 64 + bRow) * 48 + bCh;
            #pragma unroll
            for (int q = 0; q < 4; q++) {
                uint32_t bh[4];
                LDSM4(bh, bbase + q * (16 * 48));
                mma_f32(acc[q * 2], ah, bh);
                mma_f32(acc[q * 2 + 1], ah, bh + 2);
                if (kc & 1) {
                    #pragma unroll
                    for (int s = 0; s < 2; s++) {
                        int t = q * 2 + s;
                        uint32_t rb = smb + OFF_B8L + (wn * 64 + t * 8 + g) * 48 + t4 * 4;
                        uint32_t bl[2], bhh[2];
                        bl[0] = lds32(rb); bl[1] = lds32(rb + 16);
                        rb += OFF_B8H - OFF_B8L;
                        bhh[0] = lds32(rb); bhh[1] = lds32(rb + 16);
                        mma_e4(cf[t], a8h, bl);
                        mma_e4(cf[t], a8l, bhh);
                    }
                }
            }
            __syncthreads();
        }
        #undef STAGE1

        // ---- epilogue: +corr, +b1, LN(128), GELU -> H (3 planes) ----
        float s0 = 0.f, q0 = 0.f, s1 = 0.f, q1 = 0.f;
        #pragma unroll
        for (int nt = 0; nt < 8; nt++) {
            int c = p * 256 + wn * 64 + nt * 8 + t4 * 2;
            float2 bv = __ldg((const float2*)&b1g[c]);
            acc[nt][0] += cf[nt][0] * INV2048 + bv.x;
            acc[nt][1] += cf[nt][1] * INV2048 + bv.y;
            acc[nt][2] += cf[nt][2] * INV2048 + bv.x;
            acc[nt][3] += cf[nt][3] * INV2048 + bv.y;
            s0 += acc[nt][0] + acc[nt][1];
            q0 = fmaf(acc[nt][0], acc[nt][0], fmaf(acc[nt][1], acc[nt][1], q0));
            s1 += acc[nt][2] + acc[nt][3];
            q1 = fmaf(acc[nt][2], acc[nt][2], fmaf(acc[nt][3], acc[nt][3], q1));
        }
        #pragma unroll
        for (int o = 1; o <= 2; o <<= 1) {
            s0 += __shfl_xor_sync(0xffffffffu, s0, o);
            q0 += __shfl_xor_sync(0xffffffffu, q0, o);
            s1 += __shfl_xor_sync(0xffffffffu, s1, o);
            q1 += __shfl_xor_sync(0xffffffffu, q1, o);
        }
        const int rA = wm * 16 + g, rB = rA + 8;
        if (t4 == 0) {
            lns[wn * 64 + rA] = s0; lnq[wn * 64 + rA] = q0;
            lns[wn * 64 + rB] = s1; lnq[wn * 64 + rB] = q1;
        }
        __syncthreads();
        const int pw = wn ^ 1;
        float s0t = s0 + lns[pw * 64 + rA], q0t = q0 + lnq[pw * 64 + rA];
        float s1t = s1 + lns[pw * 64 + rB], q1t = q1 + lnq[pw * 64 + rB];
        const float mean0 = s0t * (1.f / 128.f);
        const float inv0  = rsqrtf(q0t * (1.f / 128.f) - mean0 * mean0 + 1e-5f);
        const float mean1 = s1t * (1.f / 128.f);
        const float inv1  = rsqrtf(q1t * (1.f / 128.f) - mean1 * mean1 + 1e-5f);
        #pragma unroll
        for (int nt = 0; nt < 8; nt++) {
            int c = p * 256 + wn * 64 + nt * 8 + t4 * 2;
            float2 gv = __ldg((const float2*)&gammag[c]);
            float2 ev = __ldg((const float2*)&betag[c]);
            float t0 = (acc[nt][0] - mean0) * inv0 * gv.x + ev.x;
            float t1 = (acc[nt][1] - mean0) * inv0 * gv.y + ev.y;
            float t2 = (acc[nt][2] - mean1) * inv1 * gv.x + ev.x;
            float t3 = (acc[nt][3] - mean1) * inv1 * gv.y + ev.y;
            t0 = 0.5f * t0 * (1.f + erff(t0 * 0.70710678118654752f));
            t1 = 0.5f * t1 * (1.f + erff(t1 * 0.70710678118654752f));
            t2 = 0.5f * t2 * (1.f + erff(t2 * 0.70710678118654752f));
            t3 = 0.5f * t3 * (1.f + erff(t3 * 0.70710678118654752f));
            __half x0 = __float2half_rn(t0), x1 = __float2half_rn(t1);
            __half x2 = __float2half_rn(t2), x3 = __float2half_rn(t3);
            *(uint32_t*)(sm + rA * HSTR + c * 2) = packh(x0, x1);
            *(uint32_t*)(sm + rB * HSTR + c * 2) = packh(x2, x3);
            *(uint16_t*)(sm + OFF_H8L + rA * H8STR + c) =
                pack8((t0 - __half2float(x0)) * 2048.f, (t1 - __half2float(x1)) * 2048.f);
            *(uint16_t*)(sm + OFF_H8L + rB * H8STR + c) =
                pack8((t2 - __half2float(x2)) * 2048.f, (t3 - __half2float(x3)) * 2048.f);
            *(uint16_t*)(sm + OFF_H8H + rA * H8STR + c) = pack8(t0, t1);
            *(uint16_t*)(sm + OFF_H8H + rB * H8STR + c) = pack8(t2, t3);
        }
        __syncthreads();
    }

    // ================= stage-1: G[n] = H[n] @ W2[n]^T + b2 =================
    float acc1[8][4], cf1[8][4];
    #pragma unroll
    for (int i = 0; i < 8; i++)
        #pragma unroll
        for (int j = 0; j < 4; j++) { acc1[i][j] = 0.f; cf1[i][j] = 0.f; }

    #define STAGEW2(kc_, buf_) do { \
        int _kc = (kc_), _bf = (buf_); \
        { int n = tid & 255, h16 = tid >> 8; \
          const __half* src = g_W2h + (size_t)n * MH + _kc * 16 + h16 * 8; \
          CPA(smb + OFF_BB + _bf * BBUF + n * 48 + h16 * 16, src); } \
        if (_kc & 1) { \
          _Pragma("unroll") \
          for (int t = 0; t < 2; t++) { \
            int comp = tid + t * 512; \
            int n = comp & 255, h16 = (comp >> 8) & 1, pl = comp >> 9; \
            const uint8_t* src = (pl ? g_W2h8 : g_W2l8) + (size_t)n * MH + (_kc >> 1) * 32 + h16 * 16; \
            CPA(smb + (pl ? OFF_B8H : OFF_B8L) + n * 48 + h16 * 16, src); \
          } } \
    } while (0)

    STAGEW2(0, 0); CPC();
    for (int kc = 0; kc < 8; kc++) {
        if (kc < 7) { STAGEW2(kc + 1, (kc + 1) & 1); CPC(); CPW1(); } else { CPW0(); }
        __syncthreads();
        const int buf = kc & 1;
        uint32_t ah[4], a8l[4], a8h[4];
        LDSM4(ah, smb + (wm * 16 + aRow) * HSTR + wn * 256 + kc * 32 + aCh);
        if (kc & 1) {
            uint32_t r0 = smb + OFF_H8L + (wm * 16 + g) * H8STR + wn * 128 + (kc >> 1) * 32 + t4 * 4;
            a8l[0] = lds32(r0); a8l[1] = lds32(r0 + 8 * H8STR); a8l[2] = lds32(r0 + 16); a8l[3] = lds32(r0 + 8 * H8STR + 16);
            r0 += OFF_H8H - OFF_H8L;
            a8h[0] = lds32(r0); a8h[1] = lds32(r0 + 8 * H8STR); a8h[2] = lds32(r0 + 16); a8h[3] = lds32(r0 + 8 * H8STR + 16);
        }
        uint32_t bbase = smb + OFF_BB + buf * BBUF + (wn * 64 + bRow) * 48 + bCh;
        #pragma unroll
        for (int q = 0; q < 4; q++) {
            uint32_t bh[4];
            LDSM4(bh, bbase + q * (16 * 48));
            mma_f32(acc1[q * 2], ah, bh);
            mma_f32(acc1[q * 2 + 1], ah, bh + 2);
            if (kc & 1) {
                #pragma unroll
                for (int s = 0; s < 2; s++) {
                    int t = q * 2 + s;
                    uint32_t rb = smb + OFF_B8L + (wn * 64 + t * 8 + g) * 48 + t4 * 4;
                    uint32_t bl[2], bhh[2];
                    bl[0] = lds32(rb); bl[1] = lds32(rb + 16);
                    rb += OFF_B8H - OFF_B8L;
                    bhh[0] = lds32(rb); bhh[1] = lds32(rb + 16);
                    mma_e4(cf1[t], a8h, bl);
                    mma_e4(cf1[t], a8l, bhh);
                }
            }
        }
        __syncthreads();
    }
    #undef STAGEW2

    // ---- stage-1 epilogue: G -> H planes cols 0..255; u -> 256..271; pad 272..287 ----
    {
        const int rA = wm * 16 + g, rB = rA + 8;
        #pragma unroll
        for (int nt = 0; nt < 8; nt++) {
            int c = wn * 64 + nt * 8 + t4 * 2;
            float2 bv = __ldg((const float2*)&b2g[c]);
            float v0 = acc1[nt][0] + cf1[nt][0] * INV2048 + bv.x;
            float v1 = acc1[nt][1] + cf1[nt][1] * INV2048 + bv.y;
            float v2 = acc1[nt][2] + cf1[nt][2] * INV2048 + bv.x;
            float v3 = acc1[nt][3] + cf1[nt][3] * INV2048 + bv.y;
            __half x0 = __float2half_rn(v0), x1 = __float2half_rn(v1);
            __half x2 = __float2half_rn(v2), x3 = __float2half_rn(v3);
            *(uint32_t*)(sm + rA * HSTR + c * 2) = packh(x0, x1);
            *(uint32_t*)(sm + rB * HSTR + c * 2) = packh(x2, x3);
            *(uint16_t*)(sm + OFF_H8L + rA * H8STR + c) =
                pack8((v0 - __half2float(x0)) * 2048.f, (v1 - __half2float(x1)) * 2048.f);
            *(uint16_t*)(sm + OFF_H8L + rB * H8STR + c) =
                pack8((v2 - __half2float(x2)) * 2048.f, (v3 - __half2float(x3)) * 2048.f);
            *(uint16_t*)(sm + OFF_H8H + rA * H8STR + c) = pack8(v0, v1);
            *(uint16_t*)(sm + OFF_H8H + rB * H8STR + c) = pack8(v2, v3);
        }
        for (int idx = tid; idx < TM * 32; idx += 512) {
            int m = idx >> 5, cu = idx & 31;
            float v = (cu < 16) ? su[m * UD + cu] : 0.f;
            __half h = __float2half_rn(v);
            *(__half*)(sm + m * HSTR + 512 + cu * 2) = h;
            *(uint8_t*)(sm + OFF_H8L + m * H8STR + 256 + cu) =
                (uint8_t)pack8((v - __half2float(h)) * 2048.f, 0.f);
            *(uint8_t*)(sm + OFF_H8H + m * H8STR + 256 + cu) = (uint8_t)pack8(v, 0.f);
        }
    }
    __syncthreads();

    // ================= stage-2: [z|yt][64][288] = [G|u|0][64][288] x B3^T =================
    float acc2[9][4], cf2[9][4];
    #pragma unroll
    for (int i = 0; i < 9; i++)
        #pragma unroll
        for (int j = 0; j < 4; j++) { acc2[i][j] = 0.f; cf2[i][j] = 0.f; }

    #define STAGE3(kc_, buf_) do { \
        int _kc = (kc_), _bf = (buf_); \
        for (int idx = tid; idx < 576; idx += 512) { \
            int n = idx >> 1, h16 = idx & 1; \
            const __half* src = g_B3h + (size_t)n * K3P + _kc * 16 + h16 * 8; \
            CPA(smb + OFF_BB + _bf * BBUF + n * 48 + h16 * 16, src); \
        } \
        if (_kc & 1) { \
          for (int idx = tid; idx < 1152; idx += 512) { \
            int pl = idx / 576, rem = idx % 576, n = rem >> 1, h16 = rem & 1; \
            const uint8_t* src = (pl ? g_B3h8 : g_B3l8) + (size_t)n * K3P + (_kc >> 1) * 32 + h16 * 16; \
            CPA(smb + (pl ? OFF_B8H : OFF_B8L) + n * 48 + h16 * 16, src); \
          } } \
    } while (0)

    STAGE3(0, 0); CPC();
    for (int kc = 0; kc < 18; kc++) {
        if (kc < 17) { STAGE3(kc + 1, (kc + 1) & 1); CPC(); CPW1(); } else { CPW0(); }
        __syncthreads();
        const int buf = kc & 1;
        uint32_t ah[4], a8l[4], a8h[4];
        LDSM4(ah, smb + (wm * 16 + aRow) * HSTR + kc * 32 + aCh);
        if (kc & 1) {
            uint32_t r0 = smb + OFF_H8L + (wm * 16 + g) * H8STR + (kc >> 1) * 32 + t4 * 4;
            a8l[0] = lds32(r0); a8l[1] = lds32(r0 + 8 * H8STR); a8l[2] = lds32(r0 + 16); a8l[3] = lds32(r0 + 8 * H8STR + 16);
            r0 += OFF_H8H - OFF_H8L;
            a8h[0] = lds32(r0); a8h[1] = lds32(r0 + 8 * H8STR); a8h[2] = lds32(r0 + 16); a8h[3] = lds32(r0 + 8 * H8STR + 16);
        }
        uint32_t bbase = smb + OFF_BB + buf * BBUF + (wn * 72 + bRow) * 48 + bCh;
        #pragma unroll
        for (int q = 0; q < 4; q++) {
            uint32_t bh[4];
            LDSM4(bh, bbase + q * (16 * 48));
            mma_f32(acc2[q * 2], ah, bh);
            mma_f32(acc2[q * 2 + 1], ah, bh + 2);
        }
        {
            uint32_t ra = smb + OFF_BB + buf * BBUF +
                          (wn * 72 + 64 + (lane & 7)) * 48 + ((lane >> 3) & 1) * 16;
            uint32_t bh[2];
            LDSM2(bh, ra);
            mma_f32(acc2[8], ah, bh);
        }
        if (kc & 1) {
            #pragma unroll
            for (int t = 0; t < 9; t++) {
                uint32_t rb = smb + OFF_B8L + (wn * 72 + t * 8 + g) * 48 + t4 * 4;
                uint32_t bl[2], bhh[2];
                bl[0] = lds32(rb); bl[1] = lds32(rb + 16);
                rb += OFF_B8H - OFF_B8L;
                bhh[0] = lds32(rb); bhh[1] = lds32(rb + 16);
                mma_e4(cf2[t], a8h, bl);
                mma_e4(cf2[t], a8l, bhh);
            }
        }
        __syncthreads();
    }
    #undef STAGE3

    // ---- epilogue: write z_next and yt ----
    float* out_yt = out + (size_t)BSZ * Dd;
    #pragma unroll
    for (int nt = 0; nt < 9; nt++) {
        const int n0 = wn * 72 + nt * 8 + t4 * 2;
        const int r = wm * 16 + g;
        float v0 = acc2[nt][0] + cf2[nt][0] * INV2048;
        float v1 = acc2[nt][1] + cf2[nt][1] * INV2048;
        float v2 = acc2[nt][2] + cf2[nt][2] * INV2048;
        float v3 = acc2[nt][3] + cf2[nt][3] * INV2048;
        if (n0 < Dd) {
            *(float2*)&out[(size_t)(row0 + r) * Dd + n0]     = make_float2(v0, v1);
            *(float2*)&out[(size_t)(row0 + r + 8) * Dd + n0] = make_float2(v2, v3);
        } else {
            const int o = n0 - Dd;
            if (o < NOBS)     { out_yt[(size_t)(row0 + r) * NOBS + o]     = v0;
                                out_yt[(size_t)(row0 + r + 8) * NOBS + o] = v2; }
            if (o + 1 < NOBS) { out_yt[(size_t)(row0 + r) * NOBS + o + 1]     = v1;
                                out_yt[(size_t)(row0 + r + 8) * NOBS + o + 1] = v3; }
        }
    }
}

extern "C" void kernel_launch(void* const* d_in, const int* in_sizes, int n_in,
                              void* d_out, int out_size) {
    const float* z_dyn    = (const float*)d_in[0];
    const float* z_static = (const float*)d_in[1];
    const float* dt       = (const float*)d_in[2];
    const float* ut       = (const float*)d_in[3];
    const float* gates    = (const float*)d_in[4];
    const float* W1       = (const float*)d_in[5];
    const float* b1       = (const float*)d_in[6];
    const float* gamma    = (const float*)d_in[7];
    const float* beta     = (const float*)d_in[8];
    const float* W2       = (const float*)d_in[9];
    const float* b2       = (const float*)d_in[10];
    const float* Bmat     = (const float*)d_in[13];
    const float* Wout     = (const float*)d_in[14];
    const float* Cmat     = (const float*)d_in[15];
    const float* Dm       = (const float*)d_in[16];
    float* out = (float*)d_out;

    preK<<<1056 + NOBS + 8, 256>>>(W1, gates, W2, Wout, Bmat, Cmat, Dm);

    cudaFuncSetAttribute(skolr8, cudaFuncAttributeMaxDynamicSharedMemorySize, SMEM_TOTAL);
    skolr8<<<BSZ / TM, 512, SMEM_TOTAL>>>(z_dyn, z_static, dt, ut, b1, gamma, beta, b2, out);
}